// round 7
// baseline (speedup 1.0000x reference)
#include <cuda_runtime.h>
#include <math.h>

#define BB 2
#define NN 2048
#define DD 256
#define MROWS (BB*NN)

typedef unsigned long long u64;
__device__ __forceinline__ u64 pk2(float lo, float hi) {
    u64 r; asm("mov.b64 %0,{%1,%2};" : "=l"(r) : "f"(lo), "f"(hi)); return r;
}
__device__ __forceinline__ void fma2(u64& d, u64 a, u64 b) {
    asm("fma.rn.f32x2 %0,%1,%2,%0;" : "+l"(d) : "l"(a), "l"(b));
}
__device__ __forceinline__ float2 up2(u64 v) {
    float lo, hi; asm("mov.b64 {%0,%1},%2;" : "=f"(lo), "=f"(hi) : "l"(v));
    float2 f; f.x = lo; f.y = hi; return f;
}

__device__ float g_qp[MROWS*DD];
__device__ float g_kp[MROWS*DD];
__device__ float g_vp[MROWS*DD];
__device__ float g_av[MROWS*DD];
__device__ float g_y [MROWS*DD];
__device__ float g_wc[DD*DD];
__device__ float g_bc[DD];

/* Double-buffered GEMM: C = [A0|A1] @ [W0|W1]^T + bias.
   k<Ksplit: A0[row*lda+k], W0[col*ldw0+k]; k>=Ksplit: A1[row*lda+k-Ksplit], W1[col*ldw1+k]. */
__device__ __forceinline__ void gemm_db_body(
    const float* __restrict__ A0, const float* __restrict__ A1, int lda,
    const float* __restrict__ W0, int ldw0,
    const float* __restrict__ W1, int ldw1,
    int Ksplit, int K,
    const float* __restrict__ bias, float* __restrict__ C, int ldc)
{
    __shared__ float As[2][16*68], Bs[2][16*68];
    const int t = threadIdx.x;
    const int row0 = blockIdx.y*64, col0 = blockIdx.x*64;
    const int fr = t >> 2, fc = (t & 3) << 2;
    const int ty = t >> 4, tx = t & 15;
    u64 acc[4][2] = {};

    float4 a4 = *(const float4*)&A0[(size_t)(row0+fr)*lda + fc];
    float4 w4 = *(const float4*)&W0[(size_t)(col0+fr)*ldw0 + fc];
    {
        float* as = As[0]; float* bs = Bs[0];
        as[(fc+0)*68+fr]=a4.x; as[(fc+1)*68+fr]=a4.y; as[(fc+2)*68+fr]=a4.z; as[(fc+3)*68+fr]=a4.w;
        bs[(fc+0)*68+fr]=w4.x; bs[(fc+1)*68+fr]=w4.y; bs[(fc+2)*68+fr]=w4.z; bs[(fc+3)*68+fr]=w4.w;
    }
    __syncthreads();
    const int T = K >> 4;
    for (int kt = 0; kt < T; kt++) {
        float4 a4n, w4n;
        if (kt+1 < T) {
            int k0 = (kt+1) << 4;
            if (k0 < Ksplit) {
                a4n = *(const float4*)&A0[(size_t)(row0+fr)*lda + k0+fc];
                w4n = *(const float4*)&W0[(size_t)(col0+fr)*ldw0 + k0+fc];
            } else {
                a4n = *(const float4*)&A1[(size_t)(row0+fr)*lda + (k0-Ksplit)+fc];
                w4n = *(const float4*)&W1[(size_t)(col0+fr)*ldw1 + k0+fc];
            }
        }
        const float* as = As[kt&1]; const float* bs = Bs[kt&1];
#pragma unroll
        for (int kk = 0; kk < 16; kk++) {
            float4 a = *(const float4*)&as[kk*68 + (ty<<2)];
            ulonglong2 bb = *(const ulonglong2*)&bs[kk*68 + (tx<<2)];
            float av_[4]={a.x,a.y,a.z,a.w};
#pragma unroll
            for (int i=0;i<4;i++) {
                u64 aa = pk2(av_[i], av_[i]);
                fma2(acc[i][0], aa, bb.x);
                fma2(acc[i][1], aa, bb.y);
            }
        }
        if (kt+1 < T) {
            float* asn = As[(kt+1)&1]; float* bsn = Bs[(kt+1)&1];
            asn[(fc+0)*68+fr]=a4n.x; asn[(fc+1)*68+fr]=a4n.y; asn[(fc+2)*68+fr]=a4n.z; asn[(fc+3)*68+fr]=a4n.w;
            bsn[(fc+0)*68+fr]=w4n.x; bsn[(fc+1)*68+fr]=w4n.y; bsn[(fc+2)*68+fr]=w4n.z; bsn[(fc+3)*68+fr]=w4n.w;
        }
        __syncthreads();
    }
    const float4 bb = *(const float4*)&bias[col0 + (tx<<2)];
#pragma unroll
    for (int i=0;i<4;i++) {
        float2 c01 = up2(acc[i][0]), c23 = up2(acc[i][1]);
        float4 o = {c01.x+bb.x, c01.y+bb.y, c23.x+bb.z, c23.y+bb.w};
        *(float4*)&C[(size_t)(row0+(ty<<2)+i)*ldc + col0 + (tx<<2)] = o;
    }
}

__global__ __launch_bounds__(256) void gemm_qkv_k(
    const float* __restrict__ q, const float* __restrict__ k, const float* __restrict__ v,
    const float* __restrict__ Wq, const float* __restrict__ bq,
    const float* __restrict__ Wk, const float* __restrict__ bk,
    const float* __restrict__ Wv, const float* __restrict__ bv,
    float* __restrict__ qp, float* __restrict__ kp, float* __restrict__ vp)
{
    const float *A, *W, *bias; float* C;
    if (blockIdx.z == 0) { A=q; W=Wq; bias=bq; C=qp; }
    else if (blockIdx.z == 1) { A=k; W=Wk; bias=bk; C=kp; }
    else { A=v; W=Wv; bias=bv; C=vp; }
    gemm_db_body(A, A, DD, W, DD, W, DD, DD, DD, bias, C, DD);
}

/* y = av @ Wc^T + q @ W1b^T + bc   (single fused GEMM, K=512) */
__global__ __launch_bounds__(256) void gemm_fin_k(
    const float* __restrict__ av, const float* __restrict__ q,
    const float* __restrict__ wc, const float* __restrict__ Wfc1,
    const float* __restrict__ bc, float* __restrict__ y)
{
    gemm_db_body(av, q, DD, wc, DD, Wfc1, 2*DD, DD, 2*DD, bc, y, DD);
}

/* Wc[j][i] = sum_k Wfc1[j][k] * Wfc[k][i]   (256x256x256) */
__global__ __launch_bounds__(256) void wcomb_k(
    const float* __restrict__ Wfc1, const float* __restrict__ Wfc, float* __restrict__ wc)
{
    __shared__ float As[16*68], Bs[16*68];
    const int t = threadIdx.x;
    const int row0 = blockIdx.y*64, col0 = blockIdx.x*64;
    const int fr = t >> 2, fc = (t & 3) << 2;   /* A tile: 64 rows x 16 k */
    const int kr = t >> 4, cc = (t & 15) << 2;  /* B tile: 16 k x 64 cols */
    const int ty = t >> 4, tx = t & 15;
    u64 acc[4][2] = {};
    for (int k0 = 0; k0 < DD; k0 += 16) {
        float4 a4 = *(const float4*)&Wfc1[(size_t)(row0+fr)*(2*DD) + k0+fc];
        float4 b4 = *(const float4*)&Wfc[(size_t)(k0+kr)*DD + col0+cc];
        As[(fc+0)*68+fr]=a4.x; As[(fc+1)*68+fr]=a4.y; As[(fc+2)*68+fr]=a4.z; As[(fc+3)*68+fr]=a4.w;
        Bs[kr*68+cc+0]=b4.x; Bs[kr*68+cc+1]=b4.y; Bs[kr*68+cc+2]=b4.z; Bs[kr*68+cc+3]=b4.w;
        __syncthreads();
#pragma unroll
        for (int kk = 0; kk < 16; kk++) {
            float4 a = *(float4*)&As[kk*68 + (ty<<2)];
            ulonglong2 bb = *(ulonglong2*)&Bs[kk*68 + (tx<<2)];
            float av_[4]={a.x,a.y,a.z,a.w};
#pragma unroll
            for (int i=0;i<4;i++) {
                u64 aa = pk2(av_[i], av_[i]);
                fma2(acc[i][0], aa, bb.x);
                fma2(acc[i][1], aa, bb.y);
            }
        }
        __syncthreads();
    }
#pragma unroll
    for (int i=0;i<4;i++) {
        float2 c01 = up2(acc[i][0]), c23 = up2(acc[i][1]);
        float4 o = {c01.x, c01.y, c23.x, c23.y};
        *(float4*)&wc[(size_t)(row0+(ty<<2)+i)*DD + col0 + (tx<<2)] = o;
    }
}

__global__ __launch_bounds__(256) void bc_k(
    const float* __restrict__ Wfc1, const float* __restrict__ bfc,
    const float* __restrict__ bfc1, float* __restrict__ bc)
{
    int j = threadIdx.x;
    float s = bfc1[j];
    for (int k = 0; k < DD; k += 4) {
        float4 w = *(const float4*)&Wfc1[(size_t)j*(2*DD) + k];
        float4 b = *(const float4*)&bfc[k];
        s += w.x*b.x + w.y*b.y + w.z*b.z + w.w*b.w;
    }
    bc[j] = s;
}

/* Sparse attention: one CTA per (b,row); 8 warps = 8 heads. */
__global__ __launch_bounds__(256) void sattn_k(
    const float* __restrict__ qp, const float* __restrict__ kp,
    const float* __restrict__ vp, const float* __restrict__ adj,
    float* __restrict__ attn, float* __restrict__ av)
{
    __shared__ unsigned short sidx[NN];
    __shared__ int warp_tot[8];
    __shared__ int s_cnt;

    const int t = threadIdx.x, lane = t & 31, w = t >> 5;
    const int grow = blockIdx.x;
    const int b = grow >> 11, row = grow & 2047;
    const float invT = 0.17677669529663687f;

    {
        const float* arow = adj + (size_t)b*NN*NN + (size_t)row*NN;
        float4 a0 = *(const float4*)&arow[t*8];
        float4 a1 = *(const float4*)&arow[t*8 + 4];
        float va[8] = {a0.x,a0.y,a0.z,a0.w,a1.x,a1.y,a1.z,a1.w};
        int c = 0;
#pragma unroll
        for (int e = 0; e < 8; e++) c += (va[e] > 0.f);
        int sc = c;
#pragma unroll
        for (int off = 1; off < 32; off <<= 1) {
            int vsh = __shfl_up_sync(0xffffffffu, sc, off);
            if (lane >= off) sc += vsh;
        }
        int excl = sc - c;
        if (lane == 31) warp_tot[w] = sc;
        __syncthreads();
        int base = 0;
#pragma unroll
        for (int i = 0; i < 8; i++) if (i < w) base += warp_tot[i];
        int pos = base + excl;
#pragma unroll
        for (int e = 0; e < 8; e++)
            if (va[e] > 0.f) sidx[pos++] = (unsigned short)(t*8 + e);
        if (t == 0) {
            int tot = 0;
#pragma unroll
            for (int i = 0; i < 8; i++) tot += warp_tot[i];
            s_cnt = tot;
        }
        __syncthreads();
    }
    const int cnt = s_cnt;
    const int h = w;
    float* arow_out = attn + ((size_t)(h*BB + b)*NN + row)*NN;
    const float* qrow = &qp[((size_t)(b*NN + row))*DD + h*32];

    if (cnt == 0) {
        const float u = 1.0f/2048.0f;
        float4 uv = {u,u,u,u};
#pragma unroll
        for (int i = 0; i < 16; i++)
            *(float4*)&arow_out[(i*32 + lane)*4] = uv;
        float o = 0.f;
        for (int j = 0; j < NN; j++)
            o += vp[((size_t)(b*NN + j))*DD + h*32 + lane];
        av[((size_t)(b*NN + row))*DD + h*32 + lane] = o * u;
        return;
    }

    float4 z4 = {0.f,0.f,0.f,0.f};
#pragma unroll
    for (int i = 0; i < 16; i++)
        *(float4*)&arow_out[(i*32 + lane)*4] = z4;
    __syncwarp();

    const int sub = lane >> 3;
    const int dg  = (lane & 7) << 2;
    const float4 qq = *(const float4*)&qrow[dg];
    float m = -1e30f, l = 0.f;
    for (int base = 0; base < cnt; base += 4) {
        int j = base + sub;
        bool ok = (j < cnt);
        int n = sidx[ok ? j : 0];
        float4 kv = *(const float4*)&kp[((size_t)(b*NN + n))*DD + h*32 + dg];
        float part = qq.x*kv.x + qq.y*kv.y + qq.z*kv.z + qq.w*kv.w;
        part += __shfl_xor_sync(0xffffffffu, part, 4);
        part += __shfl_xor_sync(0xffffffffu, part, 2);
        part += __shfl_xor_sync(0xffffffffu, part, 1);
        if (ok && (lane & 7) == 0) {
            float s = part * invT;
            arow_out[n] = s;
            float mn = fmaxf(m, s);
            l = l*__expf(m - mn) + __expf(s - mn);
            m = mn;
        }
    }
#pragma unroll
    for (int off = 16; off >= 1; off >>= 1) {
        float om = __shfl_xor_sync(0xffffffffu, m, off);
        float ol = __shfl_xor_sync(0xffffffffu, l, off);
        float mn = fmaxf(m, om);
        l = l*__expf(m - mn) + ol*__expf(om - mn);
        m = mn;
    }
    const float rinv = 1.0f / l;

    float o = 0.f;
    for (int base = 0; base < cnt; base += 32) {
        int j = base + lane;
        float p = 0.f; int n = 0;
        if (j < cnt) {
            n = sidx[j];
            float s = arow_out[n];
            p = __expf(s - m) * rinv;
            arow_out[n] = p;
        }
#pragma unroll 4
        for (int jj = 0; jj < 32; jj++) {
            if (base + jj >= cnt) break;
            float pb = __shfl_sync(0xffffffffu, p, jj);
            int   nb = __shfl_sync(0xffffffffu, n, jj);
            o += pb * vp[((size_t)(b*NN + nb))*DD + h*32 + lane];
        }
    }
    av[((size_t)(b*NN + row))*DD + h*32 + lane] = o;
}

__global__ __launch_bounds__(256) void ln_k(
    const float* __restrict__ x, const float* __restrict__ gamma,
    const float* __restrict__ beta, float* __restrict__ out)
{
    int row = blockIdx.x, t = threadIdx.x;
    float v = x[(size_t)row*256 + t];
    __shared__ float red[8];
    __shared__ float s_mu, s_isd;
    float s = v;
#pragma unroll
    for (int off=16; off>=1; off>>=1) s += __shfl_xor_sync(0xffffffffu, s, off);
    if ((t&31)==0) red[t>>5] = s;
    __syncthreads();
    if (t == 0) { float tt=0.f; for (int i=0;i<8;i++) tt+=red[i]; s_mu = tt*(1.f/256.f); }
    __syncthreads();
    float d = v - s_mu, q2 = d*d;
#pragma unroll
    for (int off=16; off>=1; off>>=1) q2 += __shfl_xor_sync(0xffffffffu, q2, off);
    if ((t&31)==0) red[t>>5] = q2;
    __syncthreads();
    if (t == 0) { float tt=0.f; for (int i=0;i<8;i++) tt+=red[i];
                  s_isd = 1.f/(sqrtf(tt*(1.f/255.f)) + 1e-3f); }
    __syncthreads();
    out[(size_t)row*256 + t] = d*s_isd*gamma[t] + beta[t];
}

extern "C" void kernel_launch(void* const* d_in, const int* in_sizes, int n_in,
                              void* d_out, int out_size)
{
    const float* q    = (const float*)d_in[0];
    const float* k    = (const float*)d_in[1];
    const float* v    = (const float*)d_in[2];
    const float* adj  = (const float*)d_in[3];
    const float* Wq   = (const float*)d_in[5];
    const float* bq   = (const float*)d_in[6];
    const float* Wk   = (const float*)d_in[7];
    const float* bk   = (const float*)d_in[8];
    const float* Wv   = (const float*)d_in[9];
    const float* bv   = (const float*)d_in[10];
    const float* Wfc  = (const float*)d_in[11];
    const float* bfc  = (const float*)d_in[12];
    const float* Wfc1 = (const float*)d_in[13];
    const float* bfc1 = (const float*)d_in[14];
    const float* gamma = (const float*)d_in[15];
    const float* beta  = (const float*)d_in[16];

    float* out  = (float*)d_out;
    float* attn = out + (size_t)MROWS*DD;

    float *qp,*kp,*vp,*avp,*yp,*wcp,*bcp;
    cudaGetSymbolAddress((void**)&qp,  g_qp);
    cudaGetSymbolAddress((void**)&kp,  g_kp);
    cudaGetSymbolAddress((void**)&vp,  g_vp);
    cudaGetSymbolAddress((void**)&avp, g_av);
    cudaGetSymbolAddress((void**)&yp,  g_y);
    cudaGetSymbolAddress((void**)&wcp, g_wc);
    cudaGetSymbolAddress((void**)&bcp, g_bc);

    dim3 tb(256);
    wcomb_k<<<dim3(DD/64, DD/64), tb>>>(Wfc1, Wfc, wcp);
    bc_k<<<1, tb>>>(Wfc1, bfc, bfc1, bcp);
    gemm_qkv_k<<<dim3(DD/64, MROWS/64, 3), tb>>>(q, k, v, Wq, bq, Wk, bk, Wv, bv, qp, kp, vp);
    sattn_k<<<MROWS, tb>>>(qp, kp, vp, adj, attn, avp);
    gemm_fin_k<<<dim3(DD/64, MROWS/64), tb>>>(avp, q, wcp, Wfc1, bcp, yp);
    ln_k<<<MROWS, tb>>>(yp, gamma, beta, out);
}